// round 2
// baseline (speedup 1.0000x reference)
#include <cuda_runtime.h>
#include <cstdint>
#include <cstddef>

// ---------------- problem constants ----------------
#define SEQ   4096
#define HIS_N 32768
#define TGT   2048
#define HID   512
#define INF   576          // LOC_E + TIM_E
#define UIDE  64
#define CATW  (2*HID+UIDE) // 1088
#define NSPLIT 16          // split-K for context GEMM

// ---------------- device scratch (no runtime alloc allowed) ----------------
__device__ float    g_x      [SEQ * INF];
__device__ float    g_hist   [HIS_N * INF];
__device__ float    g_history[HIS_N * HID];
__device__ float    g_gi     [SEQ * 3 * HID];
__device__ float    g_state  [(SEQ + 1) * HID];
__device__ unsigned g_flags  [SEQ * 32];
__device__ float    g_scores [(size_t)TGT * HIS_N];          // 268 MB
__device__ float    g_ctxs   [(size_t)NSPLIT * TGT * HID];   // 67 MB
__device__ float    g_ctx    [TGT * HID];
__device__ float    g_cat    [TGT * CATW];
__device__ float    g_yv     [TGT * HID];

// ---------------- fast math (FMA-pipe, avoids MUFU hotspots) ----------------
__device__ __forceinline__ float fast_exp(float x) {
    x = fmaxf(fminf(x, 88.0f), -87.0f);
    float y = x * 1.4426950408889634f;
    float r = rintf(y);
    float f = y - r;
    float p = 1.3333558146428443e-3f;
    p = fmaf(p, f, 9.6181291076284772e-3f);
    p = fmaf(p, f, 5.5504108664821580e-2f);
    p = fmaf(p, f, 2.4022650695910071e-1f);
    p = fmaf(p, f, 6.9314718055994531e-1f);
    p = fmaf(p, f, 1.0f);
    int i = (int)r;
    float s = __int_as_float((i + 127) << 23);
    return p * s;
}
__device__ __forceinline__ float fast_sigmoid(float x) {
    return 1.0f / (1.0f + fast_exp(-x));
}
__device__ __forceinline__ float fast_tanh(float x) {
    float a = fminf(fabsf(x) * 2.0f, 60.0f);
    float t = fast_exp(-a);
    float r = (1.0f - t) / (1.0f + t);
    return copysignf(r, x);
}

// ---------------- pack concat: out[rows x 576] = [a(rows x 512) | b(rows x 64)] ----------------
__global__ void pack_concat2(const float* __restrict__ a, const float* __restrict__ b,
                             float* __restrict__ out, int rows) {
    int idx = blockIdx.x * blockDim.x + threadIdx.x; // float4 index over rows*144
    int total = rows * 144;
    if (idx >= total) return;
    int r = idx / 144, c = idx % 144;
    float4 v;
    if (c < 128) v = ((const float4*)a)[(size_t)r * 128 + c];
    else         v = ((const float4*)b)[(size_t)r * 16 + (c - 128)];
    ((float4*)out)[idx] = v;
}

// ---------------- SGEMM TN: C[MxN] = act(A[MxK] @ B[NxK]^T + bias) ----------------
// BM=BN=128, BK=16, 256 threads, 8x8 micro-tile (split 4+4), double-buffered smem.
#define SPAD 132
__global__ __launch_bounds__(256, 2)
void sgemm_tn(const float* __restrict__ A, const float* __restrict__ B,
              float* __restrict__ C, int M, int N, int K,
              const float* __restrict__ bias, int act) {
    __shared__ float As[2][16][SPAD];
    __shared__ float Bs[2][16][SPAD];
    const int tid = threadIdx.x;
    const int mb = blockIdx.y * 128;
    const int nb = blockIdx.x * 128;
    const float* Ag = A + (size_t)mb * K;
    const float* Bg = B + (size_t)nb * K;
    const int lr = tid >> 2;          // 0..63
    const int lc = (tid & 3) << 2;    // 0,4,8,12
    const int tx = tid & 15;
    const int ty = tid >> 4;

    float acc[8][8];
#pragma unroll
    for (int i = 0; i < 8; i++)
#pragma unroll
        for (int j = 0; j < 8; j++) acc[i][j] = 0.0f;

    float4 a0, a1, b0, b1;
    a0 = *(const float4*)(Ag + (size_t)lr * K + lc);
    a1 = *(const float4*)(Ag + (size_t)(lr + 64) * K + lc);
    b0 = *(const float4*)(Bg + (size_t)lr * K + lc);
    b1 = *(const float4*)(Bg + (size_t)(lr + 64) * K + lc);
    As[0][lc+0][lr]=a0.x; As[0][lc+1][lr]=a0.y; As[0][lc+2][lr]=a0.z; As[0][lc+3][lr]=a0.w;
    As[0][lc+0][lr+64]=a1.x; As[0][lc+1][lr+64]=a1.y; As[0][lc+2][lr+64]=a1.z; As[0][lc+3][lr+64]=a1.w;
    Bs[0][lc+0][lr]=b0.x; Bs[0][lc+1][lr]=b0.y; Bs[0][lc+2][lr]=b0.z; Bs[0][lc+3][lr]=b0.w;
    Bs[0][lc+0][lr+64]=b1.x; Bs[0][lc+1][lr+64]=b1.y; Bs[0][lc+2][lr+64]=b1.z; Bs[0][lc+3][lr+64]=b1.w;
    __syncthreads();

    const int nk = K >> 4;
    for (int kt = 0; kt < nk; kt++) {
        const int cur = kt & 1;
        if (kt + 1 < nk) {
            const int ko = (kt + 1) << 4;
            a0 = *(const float4*)(Ag + (size_t)lr * K + ko + lc);
            a1 = *(const float4*)(Ag + (size_t)(lr + 64) * K + ko + lc);
            b0 = *(const float4*)(Bg + (size_t)lr * K + ko + lc);
            b1 = *(const float4*)(Bg + (size_t)(lr + 64) * K + ko + lc);
        }
#pragma unroll
        for (int k = 0; k < 16; k++) {
            float4 xa0 = *(const float4*)&As[cur][k][ty * 4];
            float4 xa1 = *(const float4*)&As[cur][k][ty * 4 + 64];
            float4 xb0 = *(const float4*)&Bs[cur][k][tx * 4];
            float4 xb1 = *(const float4*)&Bs[cur][k][tx * 4 + 64];
            float ar[8] = {xa0.x,xa0.y,xa0.z,xa0.w, xa1.x,xa1.y,xa1.z,xa1.w};
            float br[8] = {xb0.x,xb0.y,xb0.z,xb0.w, xb1.x,xb1.y,xb1.z,xb1.w};
#pragma unroll
            for (int i = 0; i < 8; i++)
#pragma unroll
                for (int j = 0; j < 8; j++)
                    acc[i][j] = fmaf(ar[i], br[j], acc[i][j]);
        }
        if (kt + 1 < nk) {
            const int nx = cur ^ 1;
            As[nx][lc+0][lr]=a0.x; As[nx][lc+1][lr]=a0.y; As[nx][lc+2][lr]=a0.z; As[nx][lc+3][lr]=a0.w;
            As[nx][lc+0][lr+64]=a1.x; As[nx][lc+1][lr+64]=a1.y; As[nx][lc+2][lr+64]=a1.z; As[nx][lc+3][lr+64]=a1.w;
            Bs[nx][lc+0][lr]=b0.x; Bs[nx][lc+1][lr]=b0.y; Bs[nx][lc+2][lr]=b0.z; Bs[nx][lc+3][lr]=b0.w;
            Bs[nx][lc+0][lr+64]=b1.x; Bs[nx][lc+1][lr+64]=b1.y; Bs[nx][lc+2][lr+64]=b1.z; Bs[nx][lc+3][lr+64]=b1.w;
        }
        __syncthreads();
    }

    float bb[8] = {0,0,0,0,0,0,0,0};
    if (bias) {
        float4 v0 = *(const float4*)(bias + nb + tx * 4);
        float4 v1 = *(const float4*)(bias + nb + 64 + tx * 4);
        bb[0]=v0.x; bb[1]=v0.y; bb[2]=v0.z; bb[3]=v0.w;
        bb[4]=v1.x; bb[5]=v1.y; bb[6]=v1.z; bb[7]=v1.w;
    }
#pragma unroll
    for (int ih = 0; ih < 2; ih++) {
#pragma unroll
        for (int i = 0; i < 4; i++) {
            int gr = mb + ih * 64 + ty * 4 + i;
            float* cp = C + (size_t)gr * N + nb;
#pragma unroll
            for (int jh = 0; jh < 2; jh++) {
                float4 o;
                o.x = acc[ih*4+i][jh*4+0] + bb[jh*4+0];
                o.y = acc[ih*4+i][jh*4+1] + bb[jh*4+1];
                o.z = acc[ih*4+i][jh*4+2] + bb[jh*4+2];
                o.w = acc[ih*4+i][jh*4+3] + bb[jh*4+3];
                if (act == 1) {
                    o.x = fast_tanh(o.x); o.y = fast_tanh(o.y);
                    o.z = fast_tanh(o.z); o.w = fast_tanh(o.w);
                }
                *(float4*)(cp + jh * 64 + tx * 4) = o;
            }
        }
    }
}

// ---------------- SGEMM NN split-K: Csplit[z] = A[MxK] @ B[KxN] over K-chunk z ----------------
__global__ __launch_bounds__(256, 2)
void sgemm_nn_split(const float* __restrict__ A, const float* __restrict__ B,
                    float* __restrict__ Csplit, int M, int N, int K, int ks) {
    __shared__ float As[2][16][SPAD];
    __shared__ float Bs[2][16][SPAD];
    const int tid = threadIdx.x;
    const int mb = blockIdx.y * 128;
    const int nb = blockIdx.x * 128;
    const int kbeg = blockIdx.z * ks;
    const float* Ag = A + (size_t)mb * K + kbeg;
    const float* Bg = B + (size_t)kbeg * N + nb;
    float* C = Csplit + (size_t)blockIdx.z * M * N;
    const int lr = tid >> 2;
    const int lc = (tid & 3) << 2;
    const int brow = tid >> 5;        // 0..7
    const int bcol = (tid & 31) << 2; // 0..124
    const int tx = tid & 15;
    const int ty = tid >> 4;

    float acc[8][8];
#pragma unroll
    for (int i = 0; i < 8; i++)
#pragma unroll
        for (int j = 0; j < 8; j++) acc[i][j] = 0.0f;

    float4 a0, a1, b0, b1;
    a0 = *(const float4*)(Ag + (size_t)lr * K + lc);
    a1 = *(const float4*)(Ag + (size_t)(lr + 64) * K + lc);
    b0 = *(const float4*)(Bg + (size_t)brow * N + bcol);
    b1 = *(const float4*)(Bg + (size_t)(brow + 8) * N + bcol);
    As[0][lc+0][lr]=a0.x; As[0][lc+1][lr]=a0.y; As[0][lc+2][lr]=a0.z; As[0][lc+3][lr]=a0.w;
    As[0][lc+0][lr+64]=a1.x; As[0][lc+1][lr+64]=a1.y; As[0][lc+2][lr+64]=a1.z; As[0][lc+3][lr+64]=a1.w;
    *(float4*)&Bs[0][brow][bcol]   = b0;
    *(float4*)&Bs[0][brow+8][bcol] = b1;
    __syncthreads();

    const int nk = ks >> 4;
    for (int kt = 0; kt < nk; kt++) {
        const int cur = kt & 1;
        if (kt + 1 < nk) {
            const int ko = (kt + 1) << 4;
            a0 = *(const float4*)(Ag + (size_t)lr * K + ko + lc);
            a1 = *(const float4*)(Ag + (size_t)(lr + 64) * K + ko + lc);
            b0 = *(const float4*)(Bg + (size_t)(ko + brow) * N + bcol);
            b1 = *(const float4*)(Bg + (size_t)(ko + brow + 8) * N + bcol);
        }
#pragma unroll
        for (int k = 0; k < 16; k++) {
            float4 xa0 = *(const float4*)&As[cur][k][ty * 4];
            float4 xa1 = *(const float4*)&As[cur][k][ty * 4 + 64];
            float4 xb0 = *(const float4*)&Bs[cur][k][tx * 4];
            float4 xb1 = *(const float4*)&Bs[cur][k][tx * 4 + 64];
            float ar[8] = {xa0.x,xa0.y,xa0.z,xa0.w, xa1.x,xa1.y,xa1.z,xa1.w};
            float br[8] = {xb0.x,xb0.y,xb0.z,xb0.w, xb1.x,xb1.y,xb1.z,xb1.w};
#pragma unroll
            for (int i = 0; i < 8; i++)
#pragma unroll
                for (int j = 0; j < 8; j++)
                    acc[i][j] = fmaf(ar[i], br[j], acc[i][j]);
        }
        if (kt + 1 < nk) {
            const int nx = cur ^ 1;
            As[nx][lc+0][lr]=a0.x; As[nx][lc+1][lr]=a0.y; As[nx][lc+2][lr]=a0.z; As[nx][lc+3][lr]=a0.w;
            As[nx][lc+0][lr+64]=a1.x; As[nx][lc+1][lr+64]=a1.y; As[nx][lc+2][lr+64]=a1.z; As[nx][lc+3][lr+64]=a1.w;
            *(float4*)&Bs[nx][brow][bcol]   = b0;
            *(float4*)&Bs[nx][brow+8][bcol] = b1;
        }
        __syncthreads();
    }
#pragma unroll
    for (int ih = 0; ih < 2; ih++) {
#pragma unroll
        for (int i = 0; i < 4; i++) {
            int gr = mb + ih * 64 + ty * 4 + i;
            float* cp = C + (size_t)gr * N + nb;
#pragma unroll
            for (int jh = 0; jh < 2; jh++) {
                float4 o;
                o.x = acc[ih*4+i][jh*4+0];
                o.y = acc[ih*4+i][jh*4+1];
                o.z = acc[ih*4+i][jh*4+2];
                o.w = acc[ih*4+i][jh*4+3];
                *(float4*)(cp + jh * 64 + tx * 4) = o;
            }
        }
    }
}

// ---------------- split-K reduce ----------------
__global__ void reduce_split(const float* __restrict__ in, float* __restrict__ out, int mn4) {
    int i = blockIdx.x * blockDim.x + threadIdx.x;
    if (i >= mn4) return;
    const float4* in4 = (const float4*)in;
    float4 s = in4[i];
#pragma unroll
    for (int z = 1; z < NSPLIT; z++) {
        float4 v = in4[(size_t)z * mn4 + i];
        s.x += v.x; s.y += v.y; s.z += v.z; s.w += v.w;
    }
    ((float4*)out)[i] = s;
}

// ---------------- GRU: persistent 32 CTAs, W_hh register-resident ----------------
__global__ __launch_bounds__(256)
void gru_kernel(const float* __restrict__ w_hh, const float* __restrict__ b_hh,
                const float* __restrict__ gi) {
    const int tid  = threadIdx.x;
    const int lane = tid & 31;
    const int warp = tid >> 5;
    const int bid  = blockIdx.x;
    const int kbase = bid * 16;
    __shared__ float dots[48];

    // each thread: 6 dots x 16 K-elems of W_hh in registers
    float4 wreg[6][4];
#pragma unroll
    for (int dd = 0; dd < 6; dd++) {
        int d = warp * 6 + dd;
        int off = d >> 4, kl = d & 15;
        const float4* wp = (const float4*)(w_hh + (size_t)(off * HID + kbase + kl) * HID + lane * 16);
        wreg[dd][0] = wp[0]; wreg[dd][1] = wp[1]; wreg[dd][2] = wp[2]; wreg[dd][3] = wp[3];
    }
    float bh_r = 0, bh_z = 0, bh_n = 0;
    const int kk = kbase + tid; // valid only for tid<16
    if (tid < 16) {
        bh_r = b_hh[kk]; bh_z = b_hh[HID + kk]; bh_n = b_hh[2 * HID + kk];
    }

    for (int t = 0; t < SEQ; t++) {
        // prefetch gi[t] (independent of h)
        float ir = 0, iz = 0, in_ = 0;
        if (tid < 16) {
            const float* g = gi + (size_t)t * (3 * HID);
            ir  = __ldg(g + kk);
            iz  = __ldg(g + HID + kk);
            in_ = __ldg(g + 2 * HID + kk);
        }
        if (t > 0) {
            if (tid < 32) {
                const unsigned* fp = &g_flags[(size_t)(t - 1) * 32 + tid];
                unsigned v;
                do {
                    asm volatile("ld.acquire.gpu.global.b32 %0, [%1];" : "=r"(v) : "l"(fp));
                } while (v == 0);
            }
            __syncthreads();
        }
        const float4* hp = (const float4*)(g_state + (size_t)t * HID + lane * 16);
        float4 h0 = __ldcg(hp + 0);
        float4 h1 = __ldcg(hp + 1);
        float4 h2 = __ldcg(hp + 2);
        float4 h3 = __ldcg(hp + 3);
        float s[6];
#pragma unroll
        for (int dd = 0; dd < 6; dd++) {
            float a;
            a = wreg[dd][0].x * h0.x;
            a = fmaf(wreg[dd][0].y, h0.y, a);
            a = fmaf(wreg[dd][0].z, h0.z, a);
            a = fmaf(wreg[dd][0].w, h0.w, a);
            a = fmaf(wreg[dd][1].x, h1.x, a);
            a = fmaf(wreg[dd][1].y, h1.y, a);
            a = fmaf(wreg[dd][1].z, h1.z, a);
            a = fmaf(wreg[dd][1].w, h1.w, a);
            a = fmaf(wreg[dd][2].x, h2.x, a);
            a = fmaf(wreg[dd][2].y, h2.y, a);
            a = fmaf(wreg[dd][2].z, h2.z, a);
            a = fmaf(wreg[dd][2].w, h2.w, a);
            a = fmaf(wreg[dd][3].x, h3.x, a);
            a = fmaf(wreg[dd][3].y, h3.y, a);
            a = fmaf(wreg[dd][3].z, h3.z, a);
            a = fmaf(wreg[dd][3].w, h3.w, a);
            s[dd] = a;
        }
#pragma unroll
        for (int dd = 0; dd < 6; dd++)
#pragma unroll
            for (int o = 16; o; o >>= 1)
                s[dd] += __shfl_xor_sync(0xffffffffu, s[dd], o);
        if (lane == 0) {
#pragma unroll
            for (int dd = 0; dd < 6; dd++) dots[warp * 6 + dd] = s[dd];
        }
        __syncthreads();
        if (tid < 16) {
            float hr = dots[tid] + bh_r;
            float hz = dots[16 + tid] + bh_z;
            float hn = dots[32 + tid] + bh_n;
            float r = fast_sigmoid(ir + hr);
            float z = fast_sigmoid(iz + hz);
            float n = fast_tanh(in_ + r * hn);
            float hprev = __ldcg(&g_state[(size_t)t * HID + kk]);
            float hnew = (1.0f - z) * n + z * hprev;
            asm volatile("st.global.cg.f32 [%0], %1;" ::
                         "l"(&g_state[(size_t)(t + 1) * HID + kk]), "f"(hnew));
            __threadfence();
        }
        __syncthreads();
        if (tid == 0) {
            asm volatile("st.release.gpu.global.b32 [%0], %1;" ::
                         "l"(&g_flags[(size_t)t * 32 + bid]), "r"(1u));
        }
    }
}

// ---------------- softmax over rows of 32768 (row cached in dyn smem) ----------------
__global__ void softmax_rows(float* __restrict__ sc) {
    extern __shared__ float4 rowbuf[]; // 8192 float4 = 128 KB
    __shared__ float redm[8];
    __shared__ float reds[8];
    __shared__ float bval[2];
    const int tid = threadIdx.x;
    const int lane = tid & 31, warp = tid >> 5;
    float4* src = (float4*)(sc + (size_t)blockIdx.x * HIS_N);

    float mx = -3.4e38f;
    for (int i = tid; i < 8192; i += 256) {
        float4 v = src[i];
        rowbuf[i] = v;
        mx = fmaxf(mx, fmaxf(fmaxf(v.x, v.y), fmaxf(v.z, v.w)));
    }
#pragma unroll
    for (int o = 16; o; o >>= 1) mx = fmaxf(mx, __shfl_xor_sync(0xffffffffu, mx, o));
    if (lane == 0) redm[warp] = mx;
    __syncthreads();
    if (tid == 0) {
        float m = redm[0];
#pragma unroll
        for (int i = 1; i < 8; i++) m = fmaxf(m, redm[i]);
        bval[0] = m;
    }
    __syncthreads();
    mx = bval[0];

    float sum = 0.0f;
    for (int i = tid; i < 8192; i += 256) {
        float4 v = rowbuf[i];
        v.x = fast_exp(v.x - mx); v.y = fast_exp(v.y - mx);
        v.z = fast_exp(v.z - mx); v.w = fast_exp(v.w - mx);
        rowbuf[i] = v;
        sum += v.x + v.y + v.z + v.w;
    }
#pragma unroll
    for (int o = 16; o; o >>= 1) sum += __shfl_xor_sync(0xffffffffu, sum, o);
    if (lane == 0) reds[warp] = sum;
    __syncthreads();
    if (tid == 0) {
        float t = 0;
#pragma unroll
        for (int i = 0; i < 8; i++) t += reds[i];
        bval[1] = 1.0f / t;
    }
    __syncthreads();
    float inv = bval[1];
    for (int i = tid; i < 8192; i += 256) {
        float4 v = rowbuf[i];
        v.x *= inv; v.y *= inv; v.z *= inv; v.w *= inv;
        src[i] = v;
    }
}

// ---------------- final concat: [q | context | emb_uid[uid]] ----------------
__global__ void cat_final(const float* __restrict__ q, const float* __restrict__ ctx,
                          const float* __restrict__ emb_uid, const int* __restrict__ uid,
                          float* __restrict__ out) {
    int idx = blockIdx.x * blockDim.x + threadIdx.x; // float4 over TGT*272
    if (idx >= TGT * 272) return;
    int r = idx / 272, c = idx % 272;
    float4 v;
    if (c < 128)       v = ((const float4*)q)[(size_t)r * 128 + c];
    else if (c < 256)  v = ((const float4*)ctx)[(size_t)r * 128 + (c - 128)];
    else {
        int u = uid[r];
        v = ((const float4*)emb_uid)[(size_t)u * 16 + (c - 256)];
    }
    ((float4*)out)[idx] = v;
}

// ---------------- log_softmax over rows of 512 ----------------
__global__ void logsoftmax_rows(const float* __restrict__ y, float* __restrict__ out) {
    __shared__ float redm[8];
    __shared__ float reds[8];
    __shared__ float bval[2];
    const int tid = threadIdx.x;
    const int lane = tid & 31, warp = tid >> 5;
    const float* row = y + (size_t)blockIdx.x * HID;
    float a = row[tid], b = row[256 + tid];
    float mx = fmaxf(a, b);
#pragma unroll
    for (int o = 16; o; o >>= 1) mx = fmaxf(mx, __shfl_xor_sync(0xffffffffu, mx, o));
    if (lane == 0) redm[warp] = mx;
    __syncthreads();
    if (tid == 0) {
        float m = redm[0];
#pragma unroll
        for (int i = 1; i < 8; i++) m = fmaxf(m, redm[i]);
        bval[0] = m;
    }
    __syncthreads();
    mx = bval[0];
    float s = expf(a - mx) + expf(b - mx);
#pragma unroll
    for (int o = 16; o; o >>= 1) s += __shfl_xor_sync(0xffffffffu, s, o);
    if (lane == 0) reds[warp] = s;
    __syncthreads();
    if (tid == 0) {
        float t = 0;
#pragma unroll
        for (int i = 0; i < 8; i++) t += reds[i];
        bval[1] = mx + logf(t);
    }
    __syncthreads();
    float lse = bval[1];
    float* orow = out + (size_t)blockIdx.x * HID;
    orow[tid] = a - lse;
    orow[256 + tid] = b - lse;
}

// ---------------- launcher ----------------
extern "C" void kernel_launch(void* const* d_in, const int* in_sizes, int n_in,
                              void* d_out, int out_size) {
    const float* loc  = (const float*)d_in[0];
    const float* tim  = (const float*)d_in[1];
    const float* hloc = (const float*)d_in[2];
    const float* htim = (const float*)d_in[3];
    // d_in[4] = history_count (unused by reference)
    const int*   uid  = (const int*)d_in[5];
    int base = 6;
    while (base < n_in && in_sizes[base] == 1) base++;  // skip scalar target_len/batch_size
    const float* fc_attn_w  = (const float*)d_in[base + 0];
    const float* fc_attn_b  = (const float*)d_in[base + 1];
    const float* w_ih       = (const float*)d_in[base + 2];
    const float* w_hh       = (const float*)d_in[base + 3];
    const float* b_ih       = (const float*)d_in[base + 4];
    const float* b_hh       = (const float*)d_in[base + 5];
    const float* emb_uid    = (const float*)d_in[base + 6];
    const float* fc_final_w = (const float*)d_in[base + 7];
    const float* fc_final_b = (const float*)d_in[base + 8];

    float *px, *phist, *phistory, *pgi, *pstate, *pscores, *pctxs, *pctx, *pcat, *pyv;
    unsigned* pflags;
    cudaGetSymbolAddress((void**)&px,       g_x);
    cudaGetSymbolAddress((void**)&phist,    g_hist);
    cudaGetSymbolAddress((void**)&phistory, g_history);
    cudaGetSymbolAddress((void**)&pgi,      g_gi);
    cudaGetSymbolAddress((void**)&pstate,   g_state);
    cudaGetSymbolAddress((void**)&pflags,   g_flags);
    cudaGetSymbolAddress((void**)&pscores,  g_scores);
    cudaGetSymbolAddress((void**)&pctxs,    g_ctxs);
    cudaGetSymbolAddress((void**)&pctx,     g_ctx);
    cudaGetSymbolAddress((void**)&pcat,     g_cat);
    cudaGetSymbolAddress((void**)&pyv,      g_yv);

    cudaFuncSetAttribute(softmax_rows, cudaFuncAttributeMaxDynamicSharedMemorySize, 131072);

    // reset recurrent state + barrier flags (graph-replay safe)
    cudaMemsetAsync(pstate, 0, HID * sizeof(float));
    cudaMemsetAsync(pflags, 0, SEQ * 32 * sizeof(unsigned));

    // pack concats
    pack_concat2<<<(SEQ * 144 + 255) / 256, 256>>>(loc, tim, px, SEQ);
    pack_concat2<<<(HIS_N * 144 + 255) / 256, 256>>>(hloc, htim, phist, HIS_N);

    // history = tanh(hist @ fc_attn_w^T + b) : 32768 x 512, K=576
    sgemm_tn<<<dim3(HID / 128, HIS_N / 128), 256>>>(phist, fc_attn_w, phistory,
                                                    HIS_N, HID, INF, fc_attn_b, 1);
    // gi = x @ w_ih^T + b_ih : 4096 x 1536, K=576
    sgemm_tn<<<dim3(3 * HID / 128, SEQ / 128), 256>>>(px, w_ih, pgi,
                                                      SEQ, 3 * HID, INF, b_ih, 0);
    // GRU scan
    gru_kernel<<<32, 256>>>(w_hh, b_hh, pgi);

    const float* qptr = pstate + (size_t)(SEQ - TGT + 1) * HID; // rows 2049..4096
    // scores = q @ history^T : 2048 x 32768, K=512
    sgemm_tn<<<dim3(HIS_N / 128, TGT / 128), 256>>>(qptr, phistory, pscores,
                                                    TGT, HIS_N, HID, nullptr, 0);
    // softmax rows
    softmax_rows<<<TGT, 256, 131072>>>(pscores);
    // context = attn @ history : 2048 x 512, K=32768, split-K=16
    sgemm_nn_split<<<dim3(HID / 128, TGT / 128, NSPLIT), 256>>>(pscores, phistory, pctxs,
                                                                TGT, HID, HIS_N, HIS_N / NSPLIT);
    reduce_split<<<(TGT * HID / 4 + 255) / 256, 256>>>(pctxs, pctx, TGT * HID / 4);

    // concat [q | ctx | uid_e]
    cat_final<<<(TGT * 272 + 255) / 256, 256>>>(qptr, pctx, emb_uid, uid, pcat);
    // y = cat @ fc_final_w^T + b : 2048 x 512, K=1088
    sgemm_tn<<<dim3(HID / 128, TGT / 128), 256>>>(pcat, fc_final_w, pyv,
                                                  TGT, HID, CATW, fc_final_b, 0);
    // log_softmax -> d_out
    logsoftmax_rows<<<TGT, 256>>>(pyv, (float*)d_out);

    (void)n_in; (void)out_size;
}

// round 3
// speedup vs baseline: 1.3758x; 1.3758x over previous
#include <cuda_runtime.h>
#include <cstdint>
#include <cstddef>

// ---------------- problem constants ----------------
#define SEQ   4096
#define HIS_N 32768
#define TGT   2048
#define HID   512
#define INF   576          // LOC_E + TIM_E
#define UIDE  64
#define CATW  (2*HID+UIDE) // 1088
#define NSPLIT 16          // split-K for context GEMM

#define GRU_CTAS    16
#define GRU_THREADS 512
#define DPW         6      // dots per warp (96 dots / 16 warps)

// ---------------- device scratch (no runtime alloc allowed) ----------------
__device__ float    g_x      [SEQ * INF];
__device__ float    g_hist   [HIS_N * INF];
__device__ float    g_history[HIS_N * HID];
__device__ float    g_gi     [SEQ * 3 * HID];
__device__ float    g_q      [TGT * HID];
__device__ float    g_scores [(size_t)TGT * HIS_N];          // 268 MB
__device__ float    g_ctxs   [(size_t)NSPLIT * TGT * HID];   // 67 MB
__device__ float    g_ctx    [TGT * HID];
__device__ float    g_cat    [TGT * CATW];
__device__ float    g_yv     [TGT * HID];

// ---------------- fast math (FMA-pipe, avoids MUFU hotspots) ----------------
__device__ __forceinline__ float fast_exp(float x) {
    x = fmaxf(fminf(x, 88.0f), -87.0f);
    float y = x * 1.4426950408889634f;
    float r = rintf(y);
    float f = y - r;
    float p = 1.3333558146428443e-3f;
    p = fmaf(p, f, 9.6181291076284772e-3f);
    p = fmaf(p, f, 5.5504108664821580e-2f);
    p = fmaf(p, f, 2.4022650695910071e-1f);
    p = fmaf(p, f, 6.9314718055994531e-1f);
    p = fmaf(p, f, 1.0f);
    int i = (int)r;
    float s = __int_as_float((i + 127) << 23);
    return p * s;
}
__device__ __forceinline__ float fast_sigmoid(float x) {
    return 1.0f / (1.0f + fast_exp(-x));
}
__device__ __forceinline__ float fast_tanh(float x) {
    float a = fminf(fabsf(x) * 2.0f, 60.0f);
    float t = fast_exp(-a);
    float r = (1.0f - t) / (1.0f + t);
    return copysignf(r, x);
}

__device__ __forceinline__ uint32_t smem_u32(const void* p) {
    uint32_t a;
    asm("{ .reg .u64 t; cvta.to.shared.u64 t, %1; cvt.u32.u64 %0, t; }" : "=r"(a) : "l"(p));
    return a;
}

// ---------------- pack concat: out[rows x 576] = [a(rows x 512) | b(rows x 64)] ----------------
__global__ void pack_concat2(const float* __restrict__ a, const float* __restrict__ b,
                             float* __restrict__ out, int rows) {
    int idx = blockIdx.x * blockDim.x + threadIdx.x; // float4 index over rows*144
    int total = rows * 144;
    if (idx >= total) return;
    int r = idx / 144, c = idx % 144;
    float4 v;
    if (c < 128) v = ((const float4*)a)[(size_t)r * 128 + c];
    else         v = ((const float4*)b)[(size_t)r * 16 + (c - 128)];
    ((float4*)out)[idx] = v;
}

// ---------------- SGEMM TN: C[MxN] = act(A[MxK] @ B[NxK]^T + bias) ----------------
#define SPAD 132
__global__ __launch_bounds__(256, 2)
void sgemm_tn(const float* __restrict__ A, const float* __restrict__ B,
              float* __restrict__ C, int M, int N, int K,
              const float* __restrict__ bias, int act) {
    __shared__ float As[2][16][SPAD];
    __shared__ float Bs[2][16][SPAD];
    const int tid = threadIdx.x;
    const int mb = blockIdx.y * 128;
    const int nb = blockIdx.x * 128;
    const float* Ag = A + (size_t)mb * K;
    const float* Bg = B + (size_t)nb * K;
    const int lr = tid >> 2;          // 0..63
    const int lc = (tid & 3) << 2;    // 0,4,8,12
    const int tx = tid & 15;
    const int ty = tid >> 4;

    float acc[8][8];
#pragma unroll
    for (int i = 0; i < 8; i++)
#pragma unroll
        for (int j = 0; j < 8; j++) acc[i][j] = 0.0f;

    float4 a0, a1, b0, b1;
    a0 = *(const float4*)(Ag + (size_t)lr * K + lc);
    a1 = *(const float4*)(Ag + (size_t)(lr + 64) * K + lc);
    b0 = *(const float4*)(Bg + (size_t)lr * K + lc);
    b1 = *(const float4*)(Bg + (size_t)(lr + 64) * K + lc);
    As[0][lc+0][lr]=a0.x; As[0][lc+1][lr]=a0.y; As[0][lc+2][lr]=a0.z; As[0][lc+3][lr]=a0.w;
    As[0][lc+0][lr+64]=a1.x; As[0][lc+1][lr+64]=a1.y; As[0][lc+2][lr+64]=a1.z; As[0][lc+3][lr+64]=a1.w;
    Bs[0][lc+0][lr]=b0.x; Bs[0][lc+1][lr]=b0.y; Bs[0][lc+2][lr]=b0.z; Bs[0][lc+3][lr]=b0.w;
    Bs[0][lc+0][lr+64]=b1.x; Bs[0][lc+1][lr+64]=b1.y; Bs[0][lc+2][lr+64]=b1.z; Bs[0][lc+3][lr+64]=b1.w;
    __syncthreads();

    const int nk = K >> 4;
    for (int kt = 0; kt < nk; kt++) {
        const int cur = kt & 1;
        if (kt + 1 < nk) {
            const int ko = (kt + 1) << 4;
            a0 = *(const float4*)(Ag + (size_t)lr * K + ko + lc);
            a1 = *(const float4*)(Ag + (size_t)(lr + 64) * K + ko + lc);
            b0 = *(const float4*)(Bg + (size_t)lr * K + ko + lc);
            b1 = *(const float4*)(Bg + (size_t)(lr + 64) * K + ko + lc);
        }
#pragma unroll
        for (int k = 0; k < 16; k++) {
            float4 xa0 = *(const float4*)&As[cur][k][ty * 4];
            float4 xa1 = *(const float4*)&As[cur][k][ty * 4 + 64];
            float4 xb0 = *(const float4*)&Bs[cur][k][tx * 4];
            float4 xb1 = *(const float4*)&Bs[cur][k][tx * 4 + 64];
            float ar[8] = {xa0.x,xa0.y,xa0.z,xa0.w, xa1.x,xa1.y,xa1.z,xa1.w};
            float br[8] = {xb0.x,xb0.y,xb0.z,xb0.w, xb1.x,xb1.y,xb1.z,xb1.w};
#pragma unroll
            for (int i = 0; i < 8; i++)
#pragma unroll
                for (int j = 0; j < 8; j++)
                    acc[i][j] = fmaf(ar[i], br[j], acc[i][j]);
        }
        if (kt + 1 < nk) {
            const int nx = cur ^ 1;
            As[nx][lc+0][lr]=a0.x; As[nx][lc+1][lr]=a0.y; As[nx][lc+2][lr]=a0.z; As[nx][lc+3][lr]=a0.w;
            As[nx][lc+0][lr+64]=a1.x; As[nx][lc+1][lr+64]=a1.y; As[nx][lc+2][lr+64]=a1.z; As[nx][lc+3][lr+64]=a1.w;
            Bs[nx][lc+0][lr]=b0.x; Bs[nx][lc+1][lr]=b0.y; Bs[nx][lc+2][lr]=b0.z; Bs[nx][lc+3][lr]=b0.w;
            Bs[nx][lc+0][lr+64]=b1.x; Bs[nx][lc+1][lr+64]=b1.y; Bs[nx][lc+2][lr+64]=b1.z; Bs[nx][lc+3][lr+64]=b1.w;
        }
        __syncthreads();
    }

    float bb[8] = {0,0,0,0,0,0,0,0};
    if (bias) {
        float4 v0 = *(const float4*)(bias + nb + tx * 4);
        float4 v1 = *(const float4*)(bias + nb + 64 + tx * 4);
        bb[0]=v0.x; bb[1]=v0.y; bb[2]=v0.z; bb[3]=v0.w;
        bb[4]=v1.x; bb[5]=v1.y; bb[6]=v1.z; bb[7]=v1.w;
    }
#pragma unroll
    for (int ih = 0; ih < 2; ih++) {
#pragma unroll
        for (int i = 0; i < 4; i++) {
            int gr = mb + ih * 64 + ty * 4 + i;
            float* cp = C + (size_t)gr * N + nb;
#pragma unroll
            for (int jh = 0; jh < 2; jh++) {
                float4 o;
                o.x = acc[ih*4+i][jh*4+0] + bb[jh*4+0];
                o.y = acc[ih*4+i][jh*4+1] + bb[jh*4+1];
                o.z = acc[ih*4+i][jh*4+2] + bb[jh*4+2];
                o.w = acc[ih*4+i][jh*4+3] + bb[jh*4+3];
                if (act == 1) {
                    o.x = fast_tanh(o.x); o.y = fast_tanh(o.y);
                    o.z = fast_tanh(o.z); o.w = fast_tanh(o.w);
                }
                *(float4*)(cp + jh * 64 + tx * 4) = o;
            }
        }
    }
}

// ---------------- SGEMM NN split-K: Csplit[z] = A[MxK] @ B[KxN] over K-chunk z ----------------
__global__ __launch_bounds__(256, 2)
void sgemm_nn_split(const float* __restrict__ A, const float* __restrict__ B,
                    float* __restrict__ Csplit, int M, int N, int K, int ks) {
    __shared__ float As[2][16][SPAD];
    __shared__ float Bs[2][16][SPAD];
    const int tid = threadIdx.x;
    const int mb = blockIdx.y * 128;
    const int nb = blockIdx.x * 128;
    const int kbeg = blockIdx.z * ks;
    const float* Ag = A + (size_t)mb * K + kbeg;
    const float* Bg = B + (size_t)kbeg * N + nb;
    float* C = Csplit + (size_t)blockIdx.z * M * N;
    const int lr = tid >> 2;
    const int lc = (tid & 3) << 2;
    const int brow = tid >> 5;        // 0..7
    const int bcol = (tid & 31) << 2; // 0..124
    const int tx = tid & 15;
    const int ty = tid >> 4;

    float acc[8][8];
#pragma unroll
    for (int i = 0; i < 8; i++)
#pragma unroll
        for (int j = 0; j < 8; j++) acc[i][j] = 0.0f;

    float4 a0, a1, b0, b1;
    a0 = *(const float4*)(Ag + (size_t)lr * K + lc);
    a1 = *(const float4*)(Ag + (size_t)(lr + 64) * K + lc);
    b0 = *(const float4*)(Bg + (size_t)brow * N + bcol);
    b1 = *(const float4*)(Bg + (size_t)(brow + 8) * N + bcol);
    As[0][lc+0][lr]=a0.x; As[0][lc+1][lr]=a0.y; As[0][lc+2][lr]=a0.z; As[0][lc+3][lr]=a0.w;
    As[0][lc+0][lr+64]=a1.x; As[0][lc+1][lr+64]=a1.y; As[0][lc+2][lr+64]=a1.z; As[0][lc+3][lr+64]=a1.w;
    *(float4*)&Bs[0][brow][bcol]   = b0;
    *(float4*)&Bs[0][brow+8][bcol] = b1;
    __syncthreads();

    const int nk = ks >> 4;
    for (int kt = 0; kt < nk; kt++) {
        const int cur = kt & 1;
        if (kt + 1 < nk) {
            const int ko = (kt + 1) << 4;
            a0 = *(const float4*)(Ag + (size_t)lr * K + ko + lc);
            a1 = *(const float4*)(Ag + (size_t)(lr + 64) * K + ko + lc);
            b0 = *(const float4*)(Bg + (size_t)(ko + brow) * N + bcol);
            b1 = *(const float4*)(Bg + (size_t)(ko + brow + 8) * N + bcol);
        }
#pragma unroll
        for (int k = 0; k < 16; k++) {
            float4 xa0 = *(const float4*)&As[cur][k][ty * 4];
            float4 xa1 = *(const float4*)&As[cur][k][ty * 4 + 64];
            float4 xb0 = *(const float4*)&Bs[cur][k][tx * 4];
            float4 xb1 = *(const float4*)&Bs[cur][k][tx * 4 + 64];
            float ar[8] = {xa0.x,xa0.y,xa0.z,xa0.w, xa1.x,xa1.y,xa1.z,xa1.w};
            float br[8] = {xb0.x,xb0.y,xb0.z,xb0.w, xb1.x,xb1.y,xb1.z,xb1.w};
#pragma unroll
            for (int i = 0; i < 8; i++)
#pragma unroll
                for (int j = 0; j < 8; j++)
                    acc[i][j] = fmaf(ar[i], br[j], acc[i][j]);
        }
        if (kt + 1 < nk) {
            const int nx = cur ^ 1;
            As[nx][lc+0][lr]=a0.x; As[nx][lc+1][lr]=a0.y; As[nx][lc+2][lr]=a0.z; As[nx][lc+3][lr]=a0.w;
            As[nx][lc+0][lr+64]=a1.x; As[nx][lc+1][lr+64]=a1.y; As[nx][lc+2][lr+64]=a1.z; As[nx][lc+3][lr+64]=a1.w;
            *(float4*)&Bs[nx][brow][bcol]   = b0;
            *(float4*)&Bs[nx][brow+8][bcol] = b1;
        }
        __syncthreads();
    }
#pragma unroll
    for (int ih = 0; ih < 2; ih++) {
#pragma unroll
        for (int i = 0; i < 4; i++) {
            int gr = mb + ih * 64 + ty * 4 + i;
            float* cp = C + (size_t)gr * N + nb;
#pragma unroll
            for (int jh = 0; jh < 2; jh++) {
                float4 o;
                o.x = acc[ih*4+i][jh*4+0];
                o.y = acc[ih*4+i][jh*4+1];
                o.z = acc[ih*4+i][jh*4+2];
                o.w = acc[ih*4+i][jh*4+3];
                *(float4*)(cp + jh * 64 + tx * 4) = o;
            }
        }
    }
}

// ---------------- split-K reduce ----------------
__global__ void reduce_split(const float* __restrict__ in, float* __restrict__ out, int mn4) {
    int i = blockIdx.x * blockDim.x + threadIdx.x;
    if (i >= mn4) return;
    const float4* in4 = (const float4*)in;
    float4 s = in4[i];
#pragma unroll
    for (int z = 1; z < NSPLIT; z++) {
        float4 v = in4[(size_t)z * mn4 + i];
        s.x += v.x; s.y += v.y; s.z += v.z; s.w += v.w;
    }
    ((float4*)out)[i] = s;
}

// ---------------- GRU: 16-CTA cluster, W_hh register-resident, h via DSMEM ----------------
// h layout in smem: hb[par][p], p = (k%16)*32 + k/16, so lane l reads
// hb[par][i*32+l] = h[l*16+i] conflict-free.
__global__ __launch_bounds__(GRU_THREADS, 1)
void gru_cluster(const float* __restrict__ w_hh, const float* __restrict__ b_hh,
                 const float* __restrict__ gi, float* __restrict__ q_out) {
    __shared__ float hb[2][HID];
    __shared__ float dots[96];
    const int tid  = threadIdx.x;
    const int lane = tid & 31;
    const int warp = tid >> 5;
    uint32_t rank;
    asm("mov.u32 %0, %%cluster_ctarank;" : "=r"(rank));
    const int dimbase = (int)rank * 32;

    // W_hh slice in registers: warp handles dots d = warp*6+dd, d = g*32+j
    float w[DPW][16];
#pragma unroll
    for (int dd = 0; dd < DPW; dd++) {
        int d = warp * DPW + dd;
        int g = d >> 5, j = d & 31;
        const float* wrow = w_hh + (size_t)(g * HID + dimbase + j) * HID + lane * 16;
#pragma unroll
        for (int i = 0; i < 16; i++) w[dd][i] = wrow[i];
    }
    float bh0 = 0, bh1 = 0, bh2 = 0;
    if (tid < 32) {
        bh0 = b_hh[dimbase + tid];
        bh1 = b_hh[HID + dimbase + tid];
        bh2 = b_hh[2 * HID + dimbase + tid];
    }
    for (int i = tid; i < HID; i += GRU_THREADS) hb[0][i] = 0.0f;
    const uint32_t hb_base = smem_u32(&hb[0][0]);

    asm volatile("barrier.cluster.arrive.aligned;" ::: "memory");
    float ir = 0, iz = 0, in_ = 0;
    if (tid < 32) {
        ir  = __ldg(gi + dimbase + tid);
        iz  = __ldg(gi + HID + dimbase + tid);
        in_ = __ldg(gi + 2 * HID + dimbase + tid);
    }
    asm volatile("barrier.cluster.wait.aligned;" ::: "memory");

    for (int t = 0; t < SEQ; t++) {
        const int par = t & 1;
        float acc[DPW] = {0, 0, 0, 0, 0, 0};
        const float* hrow = &hb[par][0];
#pragma unroll
        for (int i = 0; i < 16; i++) {
            float hv = hrow[i * 32 + lane];
#pragma unroll
            for (int dd = 0; dd < DPW; dd++)
                acc[dd] = fmaf(w[dd][i], hv, acc[dd]);
        }
#pragma unroll
        for (int dd = 0; dd < DPW; dd++)
#pragma unroll
            for (int o = 16; o; o >>= 1)
                acc[dd] += __shfl_xor_sync(0xffffffffu, acc[dd], o);
        if (lane == 0) {
#pragma unroll
            for (int dd = 0; dd < DPW; dd++) dots[warp * DPW + dd] = acc[dd];
        }
        __syncthreads();
        if (tid < 32) {
            float r = fast_sigmoid(ir + dots[tid] + bh0);
            float z = fast_sigmoid(iz + dots[32 + tid] + bh1);
            float n = fast_tanh(in_ + r * (dots[64 + tid] + bh2));
            int gdim = dimbase + tid;
            int p = ((gdim & 15) << 5) | (gdim >> 4);
            float hprev = hb[par][p];
            float hnew = (1.0f - z) * n + z * hprev;
            uint32_t a = hb_base + (uint32_t)(((par ^ 1) * HID + p) * 4);
#pragma unroll
            for (int c = 0; c < GRU_CTAS; c++) {
                uint32_t ra;
                asm volatile("mapa.shared::cluster.u32 %0, %1, %2;" : "=r"(ra) : "r"(a), "r"(c));
                asm volatile("st.shared::cluster.f32 [%0], %1;" :: "r"(ra), "f"(hnew));
            }
            if (t >= SEQ - TGT)
                q_out[(size_t)(t - (SEQ - TGT)) * HID + gdim] = hnew;
        }
        asm volatile("barrier.cluster.arrive.aligned;" ::: "memory");
        if (tid < 32 && t + 1 < SEQ) {
            const float* g = gi + (size_t)(t + 1) * (3 * HID);
            ir  = __ldg(g + dimbase + tid);
            iz  = __ldg(g + HID + dimbase + tid);
            in_ = __ldg(g + 2 * HID + dimbase + tid);
        }
        asm volatile("barrier.cluster.wait.aligned;" ::: "memory");
    }
}

// ---------------- softmax over rows of 32768 (row cached in dyn smem) ----------------
__global__ void softmax_rows(float* __restrict__ sc) {
    extern __shared__ float4 rowbuf[]; // 8192 float4 = 128 KB
    __shared__ float redm[8];
    __shared__ float reds[8];
    __shared__ float bval[2];
    const int tid = threadIdx.x;
    const int lane = tid & 31, warp = tid >> 5;
    float4* src = (float4*)(sc + (size_t)blockIdx.x * HIS_N);

    float mx = -3.4e38f;
    for (int i = tid; i < 8192; i += 256) {
        float4 v = src[i];
        rowbuf[i] = v;
        mx = fmaxf(mx, fmaxf(fmaxf(v.x, v.y), fmaxf(v.z, v.w)));
    }
#pragma unroll
    for (int o = 16; o; o >>= 1) mx = fmaxf(mx, __shfl_xor_sync(0xffffffffu, mx, o));
    if (lane == 0) redm[warp] = mx;
    __syncthreads();
    if (tid == 0) {
        float m = redm[0];
#pragma unroll
        for (int i = 1; i < 8; i++) m = fmaxf(m, redm[i]);
        bval[0] = m;
    }
    __syncthreads();
    mx = bval[0];

    float sum = 0.0f;
    for (int i = tid; i < 8192; i += 256) {
        float4 v = rowbuf[i];
        v.x = fast_exp(v.x - mx); v.y = fast_exp(v.y - mx);
        v.z = fast_exp(v.z - mx); v.w = fast_exp(v.w - mx);
        rowbuf[i] = v;
        sum += v.x + v.y + v.z + v.w;
    }
#pragma unroll
    for (int o = 16; o; o >>= 1) sum += __shfl_xor_sync(0xffffffffu, sum, o);
    if (lane == 0) reds[warp] = sum;
    __syncthreads();
    if (tid == 0) {
        float t = 0;
#pragma unroll
        for (int i = 0; i < 8; i++) t += reds[i];
        bval[1] = 1.0f / t;
    }
    __syncthreads();
    float inv = bval[1];
    for (int i = tid; i < 8192; i += 256) {
        float4 v = rowbuf[i];
        v.x *= inv; v.y *= inv; v.z *= inv; v.w *= inv;
        src[i] = v;
    }
}

// ---------------- final concat: [q | context | emb_uid[uid]] ----------------
__global__ void cat_final(const float* __restrict__ q, const float* __restrict__ ctx,
                          const float* __restrict__ emb_uid, const int* __restrict__ uid,
                          float* __restrict__ out) {
    int idx = blockIdx.x * blockDim.x + threadIdx.x; // float4 over TGT*272
    if (idx >= TGT * 272) return;
    int r = idx / 272, c = idx % 272;
    float4 v;
    if (c < 128)       v = ((const float4*)q)[(size_t)r * 128 + c];
    else if (c < 256)  v = ((const float4*)ctx)[(size_t)r * 128 + (c - 128)];
    else {
        int u = uid[r];
        v = ((const float4*)emb_uid)[(size_t)u * 16 + (c - 256)];
    }
    ((float4*)out)[idx] = v;
}

// ---------------- log_softmax over rows of 512 ----------------
__global__ void logsoftmax_rows(const float* __restrict__ y, float* __restrict__ out) {
    __shared__ float redm[8];
    __shared__ float reds[8];
    __shared__ float bval[2];
    const int tid = threadIdx.x;
    const int lane = tid & 31, warp = tid >> 5;
    const float* row = y + (size_t)blockIdx.x * HID;
    float a = row[tid], b = row[256 + tid];
    float mx = fmaxf(a, b);
#pragma unroll
    for (int o = 16; o; o >>= 1) mx = fmaxf(mx, __shfl_xor_sync(0xffffffffu, mx, o));
    if (lane == 0) redm[warp] = mx;
    __syncthreads();
    if (tid == 0) {
        float m = redm[0];
#pragma unroll
        for (int i = 1; i < 8; i++) m = fmaxf(m, redm[i]);
        bval[0] = m;
    }
    __syncthreads();
    mx = bval[0];
    float s = expf(a - mx) + expf(b - mx);
#pragma unroll
    for (int o = 16; o; o >>= 1) s += __shfl_xor_sync(0xffffffffu, s, o);
    if (lane == 0) reds[warp] = s;
    __syncthreads();
    if (tid == 0) {
        float t = 0;
#pragma unroll
        for (int i = 0; i < 8; i++) t += reds[i];
        bval[1] = mx + logf(t);
    }
    __syncthreads();
    float lse = bval[1];
    float* orow = out + (size_t)blockIdx.x * HID;
    orow[tid] = a - lse;
    orow[256 + tid] = b - lse;
}

// ---------------- launcher ----------------
extern "C" void kernel_launch(void* const* d_in, const int* in_sizes, int n_in,
                              void* d_out, int out_size) {
    const float* loc  = (const float*)d_in[0];
    const float* tim  = (const float*)d_in[1];
    const float* hloc = (const float*)d_in[2];
    const float* htim = (const float*)d_in[3];
    // d_in[4] = history_count (unused by reference)
    const int*   uid  = (const int*)d_in[5];
    int base = 6;
    while (base < n_in && in_sizes[base] == 1) base++;  // skip scalar target_len/batch_size
    const float* fc_attn_w  = (const float*)d_in[base + 0];
    const float* fc_attn_b  = (const float*)d_in[base + 1];
    const float* w_ih       = (const float*)d_in[base + 2];
    const float* w_hh       = (const float*)d_in[base + 3];
    const float* b_ih       = (const float*)d_in[base + 4];
    const float* b_hh       = (const float*)d_in[base + 5];
    const float* emb_uid    = (const float*)d_in[base + 6];
    const float* fc_final_w = (const float*)d_in[base + 7];
    const float* fc_final_b = (const float*)d_in[base + 8];

    float *px, *phist, *phistory, *pgi, *pq, *pscores, *pctxs, *pctx, *pcat, *pyv;
    cudaGetSymbolAddress((void**)&px,       g_x);
    cudaGetSymbolAddress((void**)&phist,    g_hist);
    cudaGetSymbolAddress((void**)&phistory, g_history);
    cudaGetSymbolAddress((void**)&pgi,      g_gi);
    cudaGetSymbolAddress((void**)&pq,       g_q);
    cudaGetSymbolAddress((void**)&pscores,  g_scores);
    cudaGetSymbolAddress((void**)&pctxs,    g_ctxs);
    cudaGetSymbolAddress((void**)&pctx,     g_ctx);
    cudaGetSymbolAddress((void**)&pcat,     g_cat);
    cudaGetSymbolAddress((void**)&pyv,      g_yv);

    cudaFuncSetAttribute(softmax_rows, cudaFuncAttributeMaxDynamicSharedMemorySize, 131072);
    cudaFuncSetAttribute(gru_cluster, cudaFuncAttributeNonPortableClusterSizeAllowed, 1);

    // pack concats
    pack_concat2<<<(SEQ * 144 + 255) / 256, 256>>>(loc, tim, px, SEQ);
    pack_concat2<<<(HIS_N * 144 + 255) / 256, 256>>>(hloc, htim, phist, HIS_N);

    // history = tanh(hist @ fc_attn_w^T + b) : 32768 x 512, K=576
    sgemm_tn<<<dim3(HID / 128, HIS_N / 128), 256>>>(phist, fc_attn_w, phistory,
                                                    HIS_N, HID, INF, fc_attn_b, 1);
    // gi = x @ w_ih^T + b_ih : 4096 x 1536, K=576
    sgemm_tn<<<dim3(3 * HID / 128, SEQ / 128), 256>>>(px, w_ih, pgi,
                                                      SEQ, 3 * HID, INF, b_ih, 0);

    // GRU scan: 16-CTA cluster, DSMEM h exchange
    {
        cudaLaunchConfig_t cfg = {};
        cfg.gridDim  = dim3(GRU_CTAS, 1, 1);
        cfg.blockDim = dim3(GRU_THREADS, 1, 1);
        cfg.dynamicSmemBytes = 0;
        cfg.stream = 0;
        cudaLaunchAttribute attrs[1];
        attrs[0].id = cudaLaunchAttributeClusterDimension;
        attrs[0].val.clusterDim.x = GRU_CTAS;
        attrs[0].val.clusterDim.y = 1;
        attrs[0].val.clusterDim.z = 1;
        cfg.attrs = attrs;
        cfg.numAttrs = 1;
        cudaLaunchKernelEx(&cfg, gru_cluster, w_hh, b_hh, (const float*)pgi, pq);
    }

    // scores = q @ history^T : 2048 x 32768, K=512
    sgemm_tn<<<dim3(HIS_N / 128, TGT / 128), 256>>>(pq, phistory, pscores,
                                                    TGT, HIS_N, HID, nullptr, 0);
    // softmax rows
    softmax_rows<<<TGT, 256, 131072>>>(pscores);
    // context = attn @ history : 2048 x 512, K=32768, split-K=16
    sgemm_nn_split<<<dim3(HID / 128, TGT / 128, NSPLIT), 256>>>(pscores, phistory, pctxs,
                                                                TGT, HID, HIS_N, HIS_N / NSPLIT);
    reduce_split<<<(TGT * HID / 4 + 255) / 256, 256>>>(pctxs, pctx, TGT * HID / 4);

    // concat [q | ctx | uid_e]
    cat_final<<<(TGT * 272 + 255) / 256, 256>>>(pq, pctx, emb_uid, uid, pcat);
    // y = cat @ fc_final_w^T + b : 2048 x 512, K=1088
    sgemm_tn<<<dim3(HID / 128, TGT / 128), 256>>>(pcat, fc_final_w, pyv,
                                                  TGT, HID, CATW, fc_final_b, 0);
    // log_softmax -> d_out
    logsoftmax_rows<<<TGT, 256>>>(pyv, (float*)d_out);

    (void)n_in; (void)out_size;
}

// round 4
// speedup vs baseline: 1.5884x; 1.1545x over previous
#include <cuda_runtime.h>
#include <cstdint>
#include <cstddef>

// ---------------- problem constants ----------------
#define SEQ   4096
#define HIS_N 32768
#define TGT   2048
#define HID   512
#define INF   576          // LOC_E + TIM_E
#define UIDE  64
#define CATW  (2*HID+UIDE) // 1088
#define NSPLIT 16          // split-K for context GEMM

#define GRU_CTAS    16
#define GRU_THREADS 512
#define DPW         6      // dots per warp (96 dots / 16 warps)

typedef unsigned long long u64;

// ---------------- device scratch (no runtime alloc allowed) ----------------
__device__ float    g_x      [SEQ * INF];
__device__ float    g_hist   [HIS_N * INF];
__device__ float    g_history[HIS_N * HID];
__device__ float    g_gi     [SEQ * 3 * HID];
__device__ float    g_q      [TGT * HID];
__device__ float    g_scores [(size_t)TGT * HIS_N];          // 268 MB
__device__ float    g_ctxs   [(size_t)NSPLIT * TGT * HID];   // 67 MB
__device__ float    g_ctx    [TGT * HID];
__device__ float    g_cat    [TGT * CATW];
__device__ float    g_yv     [TGT * HID];

// ---------------- f32x2 helpers ----------------
__device__ __forceinline__ void ffma2(u64& d, u64 a, u64 b) {
    asm("fma.rn.f32x2 %0, %1, %2, %0;" : "+l"(d) : "l"(a), "l"(b));
}
__device__ __forceinline__ u64 f2pack(float x, float y) {
    u64 v; asm("mov.b64 %0, {%1, %2};" : "=l"(v) : "f"(x), "f"(y)); return v;
}
__device__ __forceinline__ float2 f2unpack(u64 v) {
    float2 r; asm("mov.b64 {%0, %1}, %2;" : "=f"(r.x), "=f"(r.y) : "l"(v)); return r;
}

// ---------------- fast math (FMA-pipe, avoids MUFU hotspots) ----------------
__device__ __forceinline__ float fast_exp(float x) {
    x = fmaxf(fminf(x, 88.0f), -87.0f);
    float y = x * 1.4426950408889634f;
    float r = rintf(y);
    float f = y - r;
    float p = 1.3333558146428443e-3f;
    p = fmaf(p, f, 9.6181291076284772e-3f);
    p = fmaf(p, f, 5.5504108664821580e-2f);
    p = fmaf(p, f, 2.4022650695910071e-1f);
    p = fmaf(p, f, 6.9314718055994531e-1f);
    p = fmaf(p, f, 1.0f);
    int i = (int)r;
    float s = __int_as_float((i + 127) << 23);
    return p * s;
}
__device__ __forceinline__ float fast_sigmoid(float x) {
    return 1.0f / (1.0f + fast_exp(-x));
}
__device__ __forceinline__ float fast_tanh(float x) {
    float a = fminf(fabsf(x) * 2.0f, 60.0f);
    float t = fast_exp(-a);
    float r = (1.0f - t) / (1.0f + t);
    return copysignf(r, x);
}

__device__ __forceinline__ uint32_t smem_u32(const void* p) {
    uint32_t a;
    asm("{ .reg .u64 t; cvta.to.shared.u64 t, %1; cvt.u32.u64 %0, t; }" : "=r"(a) : "l"(p));
    return a;
}

// ---------------- pack concat: out[rows x 576] = [a(rows x 512) | b(rows x 64)] ----------------
__global__ void pack_concat2(const float* __restrict__ a, const float* __restrict__ b,
                             float* __restrict__ out, int rows) {
    int idx = blockIdx.x * blockDim.x + threadIdx.x;
    int total = rows * 144;
    if (idx >= total) return;
    int r = idx / 144, c = idx % 144;
    float4 v;
    if (c < 128) v = ((const float4*)a)[(size_t)r * 128 + c];
    else         v = ((const float4*)b)[(size_t)r * 16 + (c - 128)];
    ((float4*)out)[idx] = v;
}

// ---------------- f32x2 micro-kernel body shared by both GEMMs ----------------
// acc2[i][j2] = (acc[i][2*j2], acc[i][2*j2+1])
#define SPAD 132
#define MICRO_K_STEP(cur)                                                        \
    {                                                                            \
        float4 xa0 = *(const float4*)&As[cur][k][ty * 4];                        \
        float4 xa1 = *(const float4*)&As[cur][k][ty * 4 + 64];                   \
        float4 xb0 = *(const float4*)&Bs[cur][k][tx * 4];                        \
        float4 xb1 = *(const float4*)&Bs[cur][k][tx * 4 + 64];                   \
        float ar[8] = {xa0.x,xa0.y,xa0.z,xa0.w, xa1.x,xa1.y,xa1.z,xa1.w};        \
        u64 bd[4];                                                               \
        bd[0] = f2pack(xb0.x, xb0.y); bd[1] = f2pack(xb0.z, xb0.w);              \
        bd[2] = f2pack(xb1.x, xb1.y); bd[3] = f2pack(xb1.z, xb1.w);              \
        _Pragma("unroll")                                                        \
        for (int i = 0; i < 8; i++) {                                            \
            u64 ad = f2pack(ar[i], ar[i]);                                       \
            _Pragma("unroll")                                                    \
            for (int j2 = 0; j2 < 4; j2++) ffma2(acc2[i][j2], ad, bd[j2]);       \
        }                                                                        \
    }

// ---------------- SGEMM TN: C[MxN] = act(A[MxK] @ B[NxK]^T + bias) ----------------
__global__ __launch_bounds__(256, 2)
void sgemm_tn(const float* __restrict__ A, const float* __restrict__ B,
              float* __restrict__ C, int M, int N, int K,
              const float* __restrict__ bias, int act) {
    __shared__ float As[2][16][SPAD];
    __shared__ float Bs[2][16][SPAD];
    const int tid = threadIdx.x;
    const int mb = blockIdx.y * 128;
    const int nb = blockIdx.x * 128;
    const float* Ag = A + (size_t)mb * K;
    const float* Bg = B + (size_t)nb * K;
    const int lr = tid >> 2;          // 0..63
    const int lc = (tid & 3) << 2;    // 0,4,8,12
    const int tx = tid & 15;
    const int ty = tid >> 4;

    u64 acc2[8][4];
    const u64 z2 = f2pack(0.0f, 0.0f);
#pragma unroll
    for (int i = 0; i < 8; i++)
#pragma unroll
        for (int j = 0; j < 4; j++) acc2[i][j] = z2;

    float4 a0, a1, b0, b1;
    a0 = *(const float4*)(Ag + (size_t)lr * K + lc);
    a1 = *(const float4*)(Ag + (size_t)(lr + 64) * K + lc);
    b0 = *(const float4*)(Bg + (size_t)lr * K + lc);
    b1 = *(const float4*)(Bg + (size_t)(lr + 64) * K + lc);
    As[0][lc+0][lr]=a0.x; As[0][lc+1][lr]=a0.y; As[0][lc+2][lr]=a0.z; As[0][lc+3][lr]=a0.w;
    As[0][lc+0][lr+64]=a1.x; As[0][lc+1][lr+64]=a1.y; As[0][lc+2][lr+64]=a1.z; As[0][lc+3][lr+64]=a1.w;
    Bs[0][lc+0][lr]=b0.x; Bs[0][lc+1][lr]=b0.y; Bs[0][lc+2][lr]=b0.z; Bs[0][lc+3][lr]=b0.w;
    Bs[0][lc+0][lr+64]=b1.x; Bs[0][lc+1][lr+64]=b1.y; Bs[0][lc+2][lr+64]=b1.z; Bs[0][lc+3][lr+64]=b1.w;
    __syncthreads();

    const int nk = K >> 4;
    for (int kt = 0; kt < nk; kt++) {
        const int cur = kt & 1;
        if (kt + 1 < nk) {
            const int ko = (kt + 1) << 4;
            a0 = *(const float4*)(Ag + (size_t)lr * K + ko + lc);
            a1 = *(const float4*)(Ag + (size_t)(lr + 64) * K + ko + lc);
            b0 = *(const float4*)(Bg + (size_t)lr * K + ko + lc);
            b1 = *(const float4*)(Bg + (size_t)(lr + 64) * K + ko + lc);
        }
#pragma unroll
        for (int k = 0; k < 16; k++) MICRO_K_STEP(cur)
        if (kt + 1 < nk) {
            const int nx = cur ^ 1;
            As[nx][lc+0][lr]=a0.x; As[nx][lc+1][lr]=a0.y; As[nx][lc+2][lr]=a0.z; As[nx][lc+3][lr]=a0.w;
            As[nx][lc+0][lr+64]=a1.x; As[nx][lc+1][lr+64]=a1.y; As[nx][lc+2][lr+64]=a1.z; As[nx][lc+3][lr+64]=a1.w;
            Bs[nx][lc+0][lr]=b0.x; Bs[nx][lc+1][lr]=b0.y; Bs[nx][lc+2][lr]=b0.z; Bs[nx][lc+3][lr]=b0.w;
            Bs[nx][lc+0][lr+64]=b1.x; Bs[nx][lc+1][lr+64]=b1.y; Bs[nx][lc+2][lr+64]=b1.z; Bs[nx][lc+3][lr+64]=b1.w;
        }
        __syncthreads();
    }

    float bb[8] = {0,0,0,0,0,0,0,0};
    if (bias) {
        float4 v0 = *(const float4*)(bias + nb + tx * 4);
        float4 v1 = *(const float4*)(bias + nb + 64 + tx * 4);
        bb[0]=v0.x; bb[1]=v0.y; bb[2]=v0.z; bb[3]=v0.w;
        bb[4]=v1.x; bb[5]=v1.y; bb[6]=v1.z; bb[7]=v1.w;
    }
#pragma unroll
    for (int ih = 0; ih < 2; ih++) {
#pragma unroll
        for (int i = 0; i < 4; i++) {
            int gr = mb + ih * 64 + ty * 4 + i;
            float* cp = C + (size_t)gr * N + nb;
#pragma unroll
            for (int jh = 0; jh < 2; jh++) {
                float2 p0 = f2unpack(acc2[ih*4+i][jh*2+0]);
                float2 p1 = f2unpack(acc2[ih*4+i][jh*2+1]);
                float4 o;
                o.x = p0.x + bb[jh*4+0];
                o.y = p0.y + bb[jh*4+1];
                o.z = p1.x + bb[jh*4+2];
                o.w = p1.y + bb[jh*4+3];
                if (act == 1) {
                    o.x = fast_tanh(o.x); o.y = fast_tanh(o.y);
                    o.z = fast_tanh(o.z); o.w = fast_tanh(o.w);
                }
                *(float4*)(cp + jh * 64 + tx * 4) = o;
            }
        }
    }
}

// ---------------- SGEMM NN split-K: Csplit[z] = A[MxK] @ B[KxN] over K-chunk z ----------------
__global__ __launch_bounds__(256, 2)
void sgemm_nn_split(const float* __restrict__ A, const float* __restrict__ B,
                    float* __restrict__ Csplit, int M, int N, int K, int ks) {
    __shared__ float As[2][16][SPAD];
    __shared__ float Bs[2][16][SPAD];
    const int tid = threadIdx.x;
    const int mb = blockIdx.y * 128;
    const int nb = blockIdx.x * 128;
    const int kbeg = blockIdx.z * ks;
    const float* Ag = A + (size_t)mb * K + kbeg;
    const float* Bg = B + (size_t)kbeg * N + nb;
    float* C = Csplit + (size_t)blockIdx.z * M * N;
    const int lr = tid >> 2;
    const int lc = (tid & 3) << 2;
    const int brow = tid >> 5;        // 0..7
    const int bcol = (tid & 31) << 2; // 0..124
    const int tx = tid & 15;
    const int ty = tid >> 4;

    u64 acc2[8][4];
    const u64 z2 = f2pack(0.0f, 0.0f);
#pragma unroll
    for (int i = 0; i < 8; i++)
#pragma unroll
        for (int j = 0; j < 4; j++) acc2[i][j] = z2;

    float4 a0, a1, b0, b1;
    a0 = *(const float4*)(Ag + (size_t)lr * K + lc);
    a1 = *(const float4*)(Ag + (size_t)(lr + 64) * K + lc);
    b0 = *(const float4*)(Bg + (size_t)brow * N + bcol);
    b1 = *(const float4*)(Bg + (size_t)(brow + 8) * N + bcol);
    As[0][lc+0][lr]=a0.x; As[0][lc+1][lr]=a0.y; As[0][lc+2][lr]=a0.z; As[0][lc+3][lr]=a0.w;
    As[0][lc+0][lr+64]=a1.x; As[0][lc+1][lr+64]=a1.y; As[0][lc+2][lr+64]=a1.z; As[0][lc+3][lr+64]=a1.w;
    *(float4*)&Bs[0][brow][bcol]   = b0;
    *(float4*)&Bs[0][brow+8][bcol] = b1;
    __syncthreads();

    const int nk = ks >> 4;
    for (int kt = 0; kt < nk; kt++) {
        const int cur = kt & 1;
        if (kt + 1 < nk) {
            const int ko = (kt + 1) << 4;
            a0 = *(const float4*)(Ag + (size_t)lr * K + ko + lc);
            a1 = *(const float4*)(Ag + (size_t)(lr + 64) * K + ko + lc);
            b0 = *(const float4*)(Bg + (size_t)(ko + brow) * N + bcol);
            b1 = *(const float4*)(Bg + (size_t)(ko + brow + 8) * N + bcol);
        }
#pragma unroll
        for (int k = 0; k < 16; k++) MICRO_K_STEP(cur)
        if (kt + 1 < nk) {
            const int nx = cur ^ 1;
            As[nx][lc+0][lr]=a0.x; As[nx][lc+1][lr]=a0.y; As[nx][lc+2][lr]=a0.z; As[nx][lc+3][lr]=a0.w;
            As[nx][lc+0][lr+64]=a1.x; As[nx][lc+1][lr+64]=a1.y; As[nx][lc+2][lr+64]=a1.z; As[nx][lc+3][lr+64]=a1.w;
            *(float4*)&Bs[nx][brow][bcol]   = b0;
            *(float4*)&Bs[nx][brow+8][bcol] = b1;
        }
        __syncthreads();
    }
#pragma unroll
    for (int ih = 0; ih < 2; ih++) {
#pragma unroll
        for (int i = 0; i < 4; i++) {
            int gr = mb + ih * 64 + ty * 4 + i;
            float* cp = C + (size_t)gr * N + nb;
#pragma unroll
            for (int jh = 0; jh < 2; jh++) {
                float2 p0 = f2unpack(acc2[ih*4+i][jh*2+0]);
                float2 p1 = f2unpack(acc2[ih*4+i][jh*2+1]);
                float4 o; o.x = p0.x; o.y = p0.y; o.z = p1.x; o.w = p1.y;
                *(float4*)(cp + jh * 64 + tx * 4) = o;
            }
        }
    }
}

// ---------------- split-K reduce ----------------
__global__ void reduce_split(const float* __restrict__ in, float* __restrict__ out, int mn4) {
    int i = blockIdx.x * blockDim.x + threadIdx.x;
    if (i >= mn4) return;
    const float4* in4 = (const float4*)in;
    float4 s = in4[i];
#pragma unroll
    for (int z = 1; z < NSPLIT; z++) {
        float4 v = in4[(size_t)z * mn4 + i];
        s.x += v.x; s.y += v.y; s.z += v.z; s.w += v.w;
    }
    ((float4*)out)[i] = s;
}

// ---------------- GRU: 16-CTA cluster, f32x2 matvec, DSMEM mbarrier sync ----------------
// h stored as float2 pairs: hb2[par][m*32 + l] = (h[l*16+2m], h[l*16+2m+1])
__global__ __launch_bounds__(GRU_THREADS, 1)
void gru_cluster(const float* __restrict__ w_hh, const float* __restrict__ b_hh,
                 const float* __restrict__ gi, float* __restrict__ q_out) {
    __shared__ float2 hb2[2][HID / 2];
    __shared__ float dots[96];
    __shared__ __align__(8) unsigned long long mbar;
    const int tid  = threadIdx.x;
    const int lane = tid & 31;
    const int warp = tid >> 5;
    uint32_t rank;
    asm("mov.u32 %0, %%cluster_ctarank;" : "=r"(rank));
    const int dimbase = (int)rank * 32;

    // W_hh slice, packed pairs: warp handles dots d = warp*6+dd, d = g*32+j
    u64 w2[DPW][8];
#pragma unroll
    for (int dd = 0; dd < DPW; dd++) {
        int d = warp * DPW + dd;
        int g = d >> 5, j = d & 31;
        const float* wrow = w_hh + (size_t)(g * HID + dimbase + j) * HID + lane * 16;
#pragma unroll
        for (int m = 0; m < 8; m++)
            w2[dd][m] = f2pack(wrow[2 * m], wrow[2 * m + 1]);
    }
    float bh0 = 0, bh1 = 0, bh2 = 0;
    if (tid < 32) {
        bh0 = b_hh[dimbase + tid];
        bh1 = b_hh[HID + dimbase + tid];
        bh2 = b_hh[2 * HID + dimbase + tid];
    }
    for (int i = tid; i < HID / 2; i += GRU_THREADS) hb2[0][i] = make_float2(0.0f, 0.0f);
    const uint32_t hb_base = smem_u32(&hb2[0][0]);
    const uint32_t mbar_a  = smem_u32(&mbar);
    if (tid == 0) {
        asm volatile("mbarrier.init.shared.b64 [%0], %1;" :: "r"(mbar_a), "r"(GRU_CTAS) : "memory");
    }
    __syncthreads();
    asm volatile("barrier.cluster.arrive.aligned;" ::: "memory");

    float ir = 0, iz = 0, in_ = 0;
    if (tid < 32) {
        ir  = __ldg(gi + dimbase + tid);
        iz  = __ldg(gi + HID + dimbase + tid);
        in_ = __ldg(gi + 2 * HID + dimbase + tid);
    }
    asm volatile("barrier.cluster.wait.aligned;" ::: "memory");

    for (int t = 0; t < SEQ; t++) {
        const int par = t & 1;
        u64 acc2[DPW];
        const u64 z2 = f2pack(0.0f, 0.0f);
#pragma unroll
        for (int dd = 0; dd < DPW; dd++) acc2[dd] = z2;
        const float2* hrow = &hb2[par][0];
#pragma unroll
        for (int m = 0; m < 8; m++) {
            float2 hp = hrow[m * 32 + lane];
            u64 hv = f2pack(hp.x, hp.y);
#pragma unroll
            for (int dd = 0; dd < DPW; dd++) ffma2(acc2[dd], w2[dd][m], hv);
        }
        float s[DPW];
#pragma unroll
        for (int dd = 0; dd < DPW; dd++) {
            float2 f = f2unpack(acc2[dd]);
            s[dd] = f.x + f.y;
        }
#pragma unroll
        for (int dd = 0; dd < DPW; dd++)
#pragma unroll
            for (int o = 16; o; o >>= 1)
                s[dd] += __shfl_xor_sync(0xffffffffu, s[dd], o);
        if (lane == 0) {
#pragma unroll
            for (int dd = 0; dd < DPW; dd++) dots[warp * DPW + dd] = s[dd];
        }
        __syncthreads();
        if (tid < 32) {
            float r = fast_sigmoid(ir + dots[tid] + bh0);
            float z = fast_sigmoid(iz + dots[32 + tid] + bh1);
            float n = fast_tanh(in_ + dots[64 + tid] * r + bh2 * r);
            int gdim = dimbase + tid;
            int l = gdim >> 4, i = gdim & 15, m = i >> 1, half = i & 1;
            int fidx = (m * 32 + l) * 2 + half;
            float hprev = ((const float*)&hb2[par][0])[fidx];
            float hnew = (1.0f - z) * n + z * hprev;
            uint32_t a = hb_base + (uint32_t)(((par ^ 1) * HID + fidx) * 4);
#pragma unroll
            for (int c = 0; c < GRU_CTAS; c++) {
                uint32_t ra;
                asm volatile("mapa.shared::cluster.u32 %0, %1, %2;" : "=r"(ra) : "r"(a), "r"(c));
                asm volatile("st.shared::cluster.f32 [%0], %1;" :: "r"(ra), "f"(hnew));
            }
            if (t >= SEQ - TGT)
                q_out[(size_t)(t - (SEQ - TGT)) * HID + gdim] = hnew;
            __syncwarp();
            if (lane < GRU_CTAS) {
                uint32_t rb;
                asm volatile("mapa.shared::cluster.u32 %0, %1, %2;" : "=r"(rb) : "r"(mbar_a), "r"(lane));
                asm volatile("mbarrier.arrive.release.cluster.shared::cluster.b64 _, [%0];" :: "r"(rb) : "memory");
            }
            if (t + 1 < SEQ) {
                const float* g = gi + (size_t)(t + 1) * (3 * HID);
                ir  = __ldg(g + dimbase + tid);
                iz  = __ldg(g + HID + dimbase + tid);
                in_ = __ldg(g + 2 * HID + dimbase + tid);
            }
        }
        {
            unsigned done = 0;
            while (!done) {
                asm volatile(
                    "{\n\t.reg .pred p;\n\t"
                    "mbarrier.try_wait.parity.acquire.cluster.shared::cta.b64 p, [%1], %2, 0x989680;\n\t"
                    "selp.b32 %0, 1, 0, p;\n\t}"
                    : "=r"(done) : "r"(mbar_a), "r"((unsigned)(t & 1)) : "memory");
            }
        }
    }
    asm volatile("barrier.cluster.arrive.aligned;" ::: "memory");
    asm volatile("barrier.cluster.wait.aligned;" ::: "memory");
}

// ---------------- softmax over rows of 32768 (row cached in dyn smem) ----------------
__global__ void softmax_rows(float* __restrict__ sc) {
    extern __shared__ float4 rowbuf[]; // 8192 float4 = 128 KB
    __shared__ float redm[8];
    __shared__ float reds[8];
    __shared__ float bval[2];
    const int tid = threadIdx.x;
    const int lane = tid & 31, warp = tid >> 5;
    float4* src = (float4*)(sc + (size_t)blockIdx.x * HIS_N);

    float mx = -3.4e38f;
    for (int i = tid; i < 8192; i += 256) {
        float4 v = src[i];
        rowbuf[i] = v;
        mx = fmaxf(mx, fmaxf(fmaxf(v.x, v.y), fmaxf(v.z, v.w)));
    }
#pragma unroll
    for (int o = 16; o; o >>= 1) mx = fmaxf(mx, __shfl_xor_sync(0xffffffffu, mx, o));
    if (lane == 0) redm[warp] = mx;
    __syncthreads();
    if (tid == 0) {
        float m = redm[0];
#pragma unroll
        for (int i = 1; i < 8; i++) m = fmaxf(m, redm[i]);
        bval[0] = m;
    }
    __syncthreads();
    mx = bval[0];

    float sum = 0.0f;
    for (int i = tid; i < 8192; i += 256) {
        float4 v = rowbuf[i];
        v.x = fast_exp(v.x - mx); v.y = fast_exp(v.y - mx);
        v.z = fast_exp(v.z - mx); v.w = fast_exp(v.w - mx);
        rowbuf[i] = v;
        sum += v.x + v.y + v.z + v.w;
    }
#pragma unroll
    for (int o = 16; o; o >>= 1) sum += __shfl_xor_sync(0xffffffffu, sum, o);
    if (lane == 0) reds[warp] = sum;
    __syncthreads();
    if (tid == 0) {
        float t = 0;
#pragma unroll
        for (int i = 0; i < 8; i++) t += reds[i];
        bval[1] = 1.0f / t;
    }
    __syncthreads();
    float inv = bval[1];
    for (int i = tid; i < 8192; i += 256) {
        float4 v = rowbuf[i];
        v.x *= inv; v.y *= inv; v.z *= inv; v.w *= inv;
        src[i] = v;
    }
}

// ---------------- final concat: [q | context | emb_uid[uid]] ----------------
__global__ void cat_final(const float* __restrict__ q, const float* __restrict__ ctx,
                          const float* __restrict__ emb_uid, const int* __restrict__ uid,
                          float* __restrict__ out) {
    int idx = blockIdx.x * blockDim.x + threadIdx.x;
    if (idx >= TGT * 272) return;
    int r = idx / 272, c = idx % 272;
    float4 v;
    if (c < 128)       v = ((const float4*)q)[(size_t)r * 128 + c];
    else if (c < 256)  v = ((const float4*)ctx)[(size_t)r * 128 + (c - 128)];
    else {
        int u = uid[r];
        v = ((const float4*)emb_uid)[(size_t)u * 16 + (c - 256)];
    }
    ((float4*)out)[idx] = v;
}

// ---------------- log_softmax over rows of 512 ----------------
__global__ void logsoftmax_rows(const float* __restrict__ y, float* __restrict__ out) {
    __shared__ float redm[8];
    __shared__ float reds[8];
    __shared__ float bval[2];
    const int tid = threadIdx.x;
    const int lane = tid & 31, warp = tid >> 5;
    const float* row = y + (size_t)blockIdx.x * HID;
    float a = row[tid], b = row[256 + tid];
    float mx = fmaxf(a, b);
#pragma unroll
    for (int o = 16; o; o >>= 1) mx = fmaxf(mx, __shfl_xor_sync(0xffffffffu, mx, o));
    if (lane == 0) redm[warp] = mx;
    __syncthreads();
    if (tid == 0) {
        float m = redm[0];
#pragma unroll
        for (int i = 1; i < 8; i++) m = fmaxf(m, redm[i]);
        bval[0] = m;
    }
    __syncthreads();
    mx = bval[0];
    float s = expf(a - mx) + expf(b - mx);
#pragma unroll
    for (int o = 16; o; o >>= 1) s += __shfl_xor_sync(0xffffffffu, s, o);
    if (lane == 0) reds[warp] = s;
    __syncthreads();
    if (tid == 0) {
        float t = 0;
#pragma unroll
        for (int i = 0; i < 8; i++) t += reds[i];
        bval[1] = mx + logf(t);
    }
    __syncthreads();
    float lse = bval[1];
    float* orow = out + (size_t)blockIdx.x * HID;
    orow[tid] = a - lse;
    orow[256 + tid] = b - lse;
}

// ---------------- launcher ----------------
extern "C" void kernel_launch(void* const* d_in, const int* in_sizes, int n_in,
                              void* d_out, int out_size) {
    const float* loc  = (const float*)d_in[0];
    const float* tim  = (const float*)d_in[1];
    const float* hloc = (const float*)d_in[2];
    const float* htim = (const float*)d_in[3];
    const int*   uid  = (const int*)d_in[5];
    int base = 6;
    while (base < n_in && in_sizes[base] == 1) base++;
    const float* fc_attn_w  = (const float*)d_in[base + 0];
    const float* fc_attn_b  = (const float*)d_in[base + 1];
    const float* w_ih       = (const float*)d_in[base + 2];
    const float* w_hh       = (const float*)d_in[base + 3];
    const float* b_ih       = (const float*)d_in[base + 4];
    const float* b_hh       = (const float*)d_in[base + 5];
    const float* emb_uid    = (const float*)d_in[base + 6];
    const float* fc_final_w = (const float*)d_in[base + 7];
    const float* fc_final_b = (const float*)d_in[base + 8];

    float *px, *phist, *phistory, *pgi, *pq, *pscores, *pctxs, *pctx, *pcat, *pyv;
    cudaGetSymbolAddress((void**)&px,       g_x);
    cudaGetSymbolAddress((void**)&phist,    g_hist);
    cudaGetSymbolAddress((void**)&phistory, g_history);
    cudaGetSymbolAddress((void**)&pgi,      g_gi);
    cudaGetSymbolAddress((void**)&pq,       g_q);
    cudaGetSymbolAddress((void**)&pscores,  g_scores);
    cudaGetSymbolAddress((void**)&pctxs,    g_ctxs);
    cudaGetSymbolAddress((void**)&pctx,     g_ctx);
    cudaGetSymbolAddress((void**)&pcat,     g_cat);
    cudaGetSymbolAddress((void**)&pyv,      g_yv);

    cudaFuncSetAttribute(softmax_rows, cudaFuncAttributeMaxDynamicSharedMemorySize, 131072);
    cudaFuncSetAttribute(gru_cluster, cudaFuncAttributeNonPortableClusterSizeAllowed, 1);

    pack_concat2<<<(SEQ * 144 + 255) / 256, 256>>>(loc, tim, px, SEQ);
    pack_concat2<<<(HIS_N * 144 + 255) / 256, 256>>>(hloc, htim, phist, HIS_N);

    sgemm_tn<<<dim3(HID / 128, HIS_N / 128), 256>>>(phist, fc_attn_w, phistory,
                                                    HIS_N, HID, INF, fc_attn_b, 1);
    sgemm_tn<<<dim3(3 * HID / 128, SEQ / 128), 256>>>(px, w_ih, pgi,
                                                      SEQ, 3 * HID, INF, b_ih, 0);

    {
        cudaLaunchConfig_t cfg = {};
        cfg.gridDim  = dim3(GRU_CTAS, 1, 1);
        cfg.blockDim = dim3(GRU_THREADS, 1, 1);
        cfg.dynamicSmemBytes = 0;
        cfg.stream = 0;
        cudaLaunchAttribute attrs[1];
        attrs[0].id = cudaLaunchAttributeClusterDimension;
        attrs[0].val.clusterDim.x = GRU_CTAS;
        attrs[0].val.clusterDim.y = 1;
        attrs[0].val.clusterDim.z = 1;
        cfg.attrs = attrs;
        cfg.numAttrs = 1;
        cudaLaunchKernelEx(&cfg, gru_cluster, w_hh, b_hh, (const float*)pgi, pq);
    }

    sgemm_tn<<<dim3(HIS_N / 128, TGT / 128), 256>>>(pq, phistory, pscores,
                                                    TGT, HIS_N, HID, nullptr, 0);
    softmax_rows<<<TGT, 256, 131072>>>(pscores);
    sgemm_nn_split<<<dim3(HID / 128, TGT / 128, NSPLIT), 256>>>(pscores, phistory, pctxs,
                                                                TGT, HID, HIS_N, HIS_N / NSPLIT);
    reduce_split<<<(TGT * HID / 4 + 255) / 256, 256>>>(pctxs, pctx, TGT * HID / 4);

    cat_final<<<(TGT * 272 + 255) / 256, 256>>>(pq, pctx, emb_uid, uid, pcat);
    sgemm_tn<<<dim3(HID / 128, TGT / 128), 256>>>(pcat, fc_final_w, pyv,
                                                  TGT, HID, CATW, fc_final_b, 0);
    logsoftmax_rows<<<TGT, 256>>>(pyv, (float*)d_out);

    (void)n_in; (void)out_size;
}